// round 1
// baseline (speedup 1.0000x reference)
#include <cuda_runtime.h>
#include <cuda_fp16.h>

#define HID 64
#define SEQT 512
#define BROWS 32
#define LDH 72            // padded halves per h row (conflict-free ldmatrix)
#define NTHREADS 384      // 12 warps: 4 x layer0, 8 x layer1

__device__ __forceinline__ unsigned smem_u32(const void* p) {
    return (unsigned)__cvta_generic_to_shared(p);
}

__device__ __forceinline__ void ldsm4(unsigned a[4], unsigned addr) {
    asm volatile("ldmatrix.sync.aligned.m8n8.x4.shared.b16 {%0,%1,%2,%3}, [%4];\n"
        : "=r"(a[0]), "=r"(a[1]), "=r"(a[2]), "=r"(a[3]) : "r"(addr));
}

__device__ __forceinline__ void mma16816(float c[4], const unsigned a[4], const unsigned b[2]) {
    asm volatile("mma.sync.aligned.m16n8k16.row.col.f32.f16.f16.f32 "
        "{%0,%1,%2,%3},{%4,%5,%6,%7},{%8,%9},{%0,%1,%2,%3};\n"
        : "+f"(c[0]), "+f"(c[1]), "+f"(c[2]), "+f"(c[3])
        : "r"(a[0]), "r"(a[1]), "r"(a[2]), "r"(a[3]), "r"(b[0]), "r"(b[1]));
}

__device__ __forceinline__ float sigf(float x) {
    return __fdividef(1.0f, 1.0f + __expf(-x));
}
__device__ __forceinline__ float tanhfast(float x) {
    // tanh(x) = 1 - 2/(exp(2x)+1); safe at both infinities
    return 1.0f - __fdividef(2.0f, 1.0f + __expf(2.0f * x));
}

__global__ void __launch_bounds__(NTHREADS, 1)
lstm2_kernel(const float* __restrict__ x,
             const float* __restrict__ w_ih0, const float* __restrict__ w_hh0,
             const float* __restrict__ b_ih0, const float* __restrict__ b_hh0,
             const float* __restrict__ w_ih1, const float* __restrict__ w_hh1,
             const float* __restrict__ b_ih1, const float* __restrict__ b_hh1,
             const float* __restrict__ w_lin, const float* __restrict__ b_lin,
             float* __restrict__ out)
{
    __shared__ __half h1buf[2][BROWS * LDH];
    __shared__ __half h2buf[2][BROWS * LDH];
    __shared__ float2 bias0p[128];   // layer0 combined bias, gate-permuted layout
    __shared__ float2 wih0p[128];    // layer0 input weights (scalar x), permuted
    __shared__ float2 bias1p[128];   // layer1 combined bias, permuted
    __shared__ float  wlin_s[HID];

    const int tid  = threadIdx.x;
    const int wid  = tid >> 5;
    const int lane = tid & 31;
    const int r0   = blockIdx.x * BROWS;

    // ---------------- init: permuted bias / w_ih0 tables ----------------
    // Physical gate-column permutation: for a tile-pair (2p,2p+1) a lane's two
    // C columns hold (i,f) and (g,o) of the SAME hidden unit.
    if (tid < 256) {
        {   // layer0: 4 warps x 64 cols: idx = w*64 + j*8 + c
            int w = tid >> 6, rem = tid & 63, j = rem >> 3, c = rem & 7;
            int u = w * 16 + (j >> 1) * 4 + (c >> 1);
            int g = (j & 1) * 2 + (c & 1);
            int row = g * HID + u;
            ((float*)bias0p)[tid] = b_ih0[row] + b_hh0[row];
            ((float*)wih0p)[tid]  = w_ih0[row];
        }
        {   // layer1: 8 warps x 32 cols: idx = w1*32 + j*8 + c
            int w1 = tid >> 5, rem = tid & 31, j = rem >> 3, c = rem & 7;
            int u = w1 * 8 + (j >> 1) * 4 + (c >> 1);
            int g = (j & 1) * 2 + (c & 1);
            int row = g * HID + u;
            ((float*)bias1p)[tid] = b_ih1[row] + b_hh1[row];
        }
    }
    if (tid < HID) wlin_s[tid] = w_lin[tid];
    for (int i = tid; i < BROWS * LDH; i += NTHREADS) {
        h1buf[1][i]  = __float2half(0.0f);
        h2buf[0][i]  = __float2half(0.0f);
        h2buf[1][i]  = __float2half(0.0f);
    }

    // ---------------- preload weight B-fragments into registers ----------------
    // B-frag (m16n8k16): lane holds col n = lane>>2; reg0 = k {2q,2q+1}, reg1 = +8 (q=lane&3)
    unsigned wf[64];
    float    cs[16];
    #pragma unroll
    for (int i = 0; i < 16; i++) cs[i] = 0.0f;

    const int cB = lane >> 2;
    const int kq = lane & 3;

    if (wid < 4) {
        const int w = wid;
        #pragma unroll
        for (int j = 0; j < 8; j++) {
            int u = w * 16 + (j >> 1) * 4 + (cB >> 1);
            int g = (j & 1) * 2 + (cB & 1);
            const float* wr = w_hh0 + (g * HID + u) * HID;
            #pragma unroll
            for (int kt = 0; kt < 4; kt++) {
                int k0 = kt * 16 + 2 * kq;
                __half2 lo = __floats2half2_rn(wr[k0],     wr[k0 + 1]);
                __half2 hi = __floats2half2_rn(wr[k0 + 8], wr[k0 + 9]);
                wf[(j * 4 + kt) * 2 + 0] = *(unsigned*)&lo;
                wf[(j * 4 + kt) * 2 + 1] = *(unsigned*)&hi;
            }
        }
    } else {
        const int w1 = wid - 4;
        #pragma unroll
        for (int m = 0; m < 2; m++) {
            const float* W = m ? w_hh1 : w_ih1;
            #pragma unroll
            for (int j = 0; j < 4; j++) {
                int u = w1 * 8 + (j >> 1) * 4 + (cB >> 1);
                int g = (j & 1) * 2 + (cB & 1);
                const float* wr = W + (g * HID + u) * HID;
                #pragma unroll
                for (int kt = 0; kt < 4; kt++) {
                    int k0 = kt * 16 + 2 * kq;
                    __half2 lo = __floats2half2_rn(wr[k0],     wr[k0 + 1]);
                    __half2 hi = __floats2half2_rn(wr[k0 + 8], wr[k0 + 9]);
                    wf[((m * 4 + j) * 4 + kt) * 2 + 0] = *(unsigned*)&lo;
                    wf[((m * 4 + j) * 4 + kt) * 2 + 1] = *(unsigned*)&hi;
                }
            }
        }
    }
    __syncthreads();

    const unsigned h1base[2] = { smem_u32(h1buf[0]), smem_u32(h1buf[1]) };
    const unsigned h2base[2] = { smem_u32(h2buf[0]), smem_u32(h2buf[1]) };

    // ---------------- pipelined time loop ----------------
    // iter k: L0 warps compute h1_k (read h1[rd], write h1[wr])
    //         L1 warps compute h2_{k-1} (read h1[rd] & h2[wr], write h2[rd])
    for (int k = 0; k <= SEQT; ++k) {
        const int rd = (k + 1) & 1;
        const int wr = k & 1;

        if (wid < 4) {
            if (k < SEQT) {
                const int w = wid;
                float xv[4];
                #pragma unroll
                for (int i = 0; i < 4; i++) {
                    int r = (lane >> 2) + 8 * (i & 1) + 16 * (i >> 1);
                    xv[i] = x[(r0 + r) * SEQT + k];
                }
                #pragma unroll
                for (int mt = 0; mt < 2; mt++) {
                    float cf[32];
                    #pragma unroll
                    for (int i = 0; i < 32; i++) cf[i] = 0.0f;
                    #pragma unroll
                    for (int kt = 0; kt < 4; kt++) {
                        unsigned am[4];
                        unsigned addr = h1base[rd] +
                            2u * ((16 * mt + (lane & 15)) * LDH + kt * 16 + (lane >> 4) * 8);
                        ldsm4(am, addr);
                        #pragma unroll
                        for (int j = 0; j < 8; j++)
                            mma16816(&cf[j * 4], am, &wf[(j * 4 + kt) * 2]);
                    }
                    #pragma unroll
                    for (int p = 0; p < 4; p++) {
                        float2 bif = bias0p[w * 32 + (2 * p) * 4 + (lane & 3)];
                        float2 bgo = bias0p[w * 32 + (2 * p + 1) * 4 + (lane & 3)];
                        float2 wif = wih0p[w * 32 + (2 * p) * 4 + (lane & 3)];
                        float2 wgo = wih0p[w * 32 + (2 * p + 1) * 4 + (lane & 3)];
                        #pragma unroll
                        for (int rh = 0; rh < 2; rh++) {
                            float xr = xv[mt * 2 + rh];
                            float ip = cf[(2 * p) * 4 + rh * 2 + 0] + bif.x + xr * wif.x;
                            float fp = cf[(2 * p) * 4 + rh * 2 + 1] + bif.y + xr * wif.y;
                            float gp = cf[(2 * p + 1) * 4 + rh * 2 + 0] + bgo.x + xr * wgo.x;
                            float op = cf[(2 * p + 1) * 4 + rh * 2 + 1] + bgo.y + xr * wgo.y;
                            int ci = mt * 8 + p * 2 + rh;
                            float c = sigf(fp) * cs[ci] + sigf(ip) * tanhfast(gp);
                            cs[ci] = c;
                            float h = sigf(op) * tanhfast(c);
                            int r = 16 * mt + (lane >> 2) + 8 * rh;
                            int u = w * 16 + 4 * p + (lane & 3);
                            h1buf[wr][r * LDH + u] = __float2half_rn(h);
                        }
                    }
                }
            }
        } else {
            if (k >= 1) {
                const int w1 = wid - 4;
                #pragma unroll
                for (int mt = 0; mt < 2; mt++) {
                    float cf[16];
                    #pragma unroll
                    for (int i = 0; i < 16; i++) cf[i] = 0.0f;
                    #pragma unroll
                    for (int kt = 0; kt < 4; kt++) {       // h1_{k-1} @ w_ih1^T
                        unsigned am[4];
                        unsigned addr = h1base[rd] +
                            2u * ((16 * mt + (lane & 15)) * LDH + kt * 16 + (lane >> 4) * 8);
                        ldsm4(am, addr);
                        #pragma unroll
                        for (int j = 0; j < 4; j++)
                            mma16816(&cf[j * 4], am, &wf[(j * 4 + kt) * 2]);
                    }
                    #pragma unroll
                    for (int kt = 0; kt < 4; kt++) {       // h2_{k-2} @ w_hh1^T
                        unsigned am[4];
                        unsigned addr = h2base[wr] +
                            2u * ((16 * mt + (lane & 15)) * LDH + kt * 16 + (lane >> 4) * 8);
                        ldsm4(am, addr);
                        #pragma unroll
                        for (int j = 0; j < 4; j++)
                            mma16816(&cf[j * 4], am, &wf[((4 + j) * 4 + kt) * 2]);
                    }
                    #pragma unroll
                    for (int p = 0; p < 2; p++) {
                        float2 bif = bias1p[w1 * 16 + (2 * p) * 4 + (lane & 3)];
                        float2 bgo = bias1p[w1 * 16 + (2 * p + 1) * 4 + (lane & 3)];
                        #pragma unroll
                        for (int rh = 0; rh < 2; rh++) {
                            float ip = cf[(2 * p) * 4 + rh * 2 + 0] + bif.x;
                            float fp = cf[(2 * p) * 4 + rh * 2 + 1] + bif.y;
                            float gp = cf[(2 * p + 1) * 4 + rh * 2 + 0] + bgo.x;
                            float op = cf[(2 * p + 1) * 4 + rh * 2 + 1] + bgo.y;
                            int ci = mt * 4 + p * 2 + rh;
                            float c = sigf(fp) * cs[ci] + sigf(ip) * tanhfast(gp);
                            cs[ci] = c;
                            float h = sigf(op) * tanhfast(c);
                            int r = 16 * mt + (lane >> 2) + 8 * rh;
                            int u = w1 * 8 + 4 * p + (lane & 3);
                            h2buf[rd][r * LDH + u] = __float2half_rn(h);
                        }
                    }
                }
            }
        }
        __syncthreads();
    }

    // ---------------- linear head on h2_{T-1} ----------------
    if (tid < BROWS) {
        const __half* h2f = h2buf[(SEQT + 1) & 1];
        float acc = b_lin[0];
        #pragma unroll
        for (int u = 0; u < HID; u++)
            acc += __half2float(h2f[tid * LDH + u]) * wlin_s[u];
        out[r0 + tid] = acc;
    }
}

extern "C" void kernel_launch(void* const* d_in, const int* in_sizes, int n_in,
                              void* d_out, int out_size) {
    const float* x     = (const float*)d_in[0];
    const float* w_ih0 = (const float*)d_in[1];
    const float* w_hh0 = (const float*)d_in[2];
    const float* b_ih0 = (const float*)d_in[3];
    const float* b_hh0 = (const float*)d_in[4];
    const float* w_ih1 = (const float*)d_in[5];
    const float* w_hh1 = (const float*)d_in[6];
    const float* b_ih1 = (const float*)d_in[7];
    const float* b_hh1 = (const float*)d_in[8];
    const float* w_lin = (const float*)d_in[9];
    const float* b_lin = (const float*)d_in[10];

    const int B = in_sizes[0] / SEQT;   // 4096
    const int grid = B / BROWS;         // 128

    lstm2_kernel<<<grid, NTHREADS>>>(x, w_ih0, w_hh0, b_ih0, b_hh0,
                                     w_ih1, w_hh1, b_ih1, b_hh1,
                                     w_lin, b_lin, (float*)d_out);
}